// round 10
// baseline (speedup 1.0000x reference)
#include <cuda_runtime.h>
#include <cuda_bf16.h>
#include <cstdint>

// Problem dims (fixed by the dataset)
#define BROWS 8192
#define DDIM  784
#define HDIM  500
#define CDIM  512
#define SDIM  16
#define CSDIM (CDIM * SDIM)      // 8192
#define NROWS2 (BROWS * SDIM)    // 131072
#define BK 16

// -------- scratch (no allocations allowed) ----
__device__ float g_h1[BROWS * HDIM];
__device__ float g_h2[BROWS * HDIM];
__device__ float g_cnorm[CDIM];
__device__ float g_rownorm[NROWS2];
__device__ int   g_codes[NROWS2];
__device__ float g_table[SDIM * CDIM * 512];              // 16.8 MB
__device__ float g_S[(size_t)NROWS2 * CDIM];              // approx dots, 268 MB
__device__ __nv_bfloat16 g_obsbf[(size_t)NROWS2 * CDIM];  // 134 MB
__device__ __nv_bfloat16 g_cbbf[CDIM * CDIM];             // 0.5 MB

// ---------------- packed f32x2 helpers (sm_100+: fma.rn.f32x2) ----------------
__device__ __forceinline__ uint64_t pack_dup(float x) {
    uint64_t r;
    asm("mov.b64 %0, {%1, %1};" : "=l"(r) : "f"(x));
    return r;
}
__device__ __forceinline__ void ffma2(uint64_t& d, uint64_t a, uint64_t b) {
    asm("fma.rn.f32x2 %0, %1, %2, %0;" : "+l"(d) : "l"(a), "l"(b));
}
__device__ __forceinline__ float2 unpack2(uint64_t v) {
    float lo, hi;
    asm("mov.b64 {%0, %1}, %2;" : "=f"(lo), "=f"(hi) : "l"(v));
    return make_float2(lo, hi);
}

// ---------------- bf16 mma helper (m16n8k16, row.col, f32 acc) ----------------
__device__ __forceinline__ void mma_bf16(float* d, const uint32_t* a,
                                         uint32_t b0, uint32_t b1) {
    asm volatile(
        "mma.sync.aligned.m16n8k16.row.col.f32.bf16.bf16.f32 "
        "{%0,%1,%2,%3}, {%4,%5,%6,%7}, {%8,%9}, {%0,%1,%2,%3};"
        : "+f"(d[0]), "+f"(d[1]), "+f"(d[2]), "+f"(d[3])
        : "r"(a[0]), "r"(a[1]), "r"(a[2]), "r"(a[3]), "r"(b0), "r"(b1));
}

// ============================================================================
// Codebook / obs row norms in DOUBLE (one warp per row)
// ============================================================================
__global__ void cnorm_kernel(const float* __restrict__ cb, float* __restrict__ cn) {
    int warp = (blockIdx.x * blockDim.x + threadIdx.x) >> 5;
    int lane = threadIdx.x & 31;
    if (warp >= CDIM) return;
    const float* row = cb + (size_t)warp * CDIM;
    double s = 0.0;
    for (int k = lane; k < CDIM; k += 32) { double v = (double)row[k]; s += v * v; }
    #pragma unroll
    for (int o = 16; o > 0; o >>= 1) s += __shfl_down_sync(0xffffffffu, s, o);
    if (lane == 0) cn[warp] = (float)s;
}

__global__ void rownorm_kernel(const float* __restrict__ obs, float* __restrict__ rn) {
    int warp = (blockIdx.x * blockDim.x + threadIdx.x) >> 5;
    int lane = threadIdx.x & 31;
    if (warp >= NROWS2) return;
    const float* row = obs + (size_t)warp * CDIM;
    double s = 0.0;
    for (int k = lane; k < CDIM; k += 32) { double v = (double)row[k]; s += v * v; }
    #pragma unroll
    for (int o = 16; o > 0; o >>= 1) s += __shfl_down_sync(0xffffffffu, s, o);
    if (lane == 0) rn[warp] = (float)s;
}

// ============================================================================
// fp32 -> bf16 conversion: 8 elements per thread (n8 groups of 8)
// ============================================================================
__global__ void convert_bf16(const float* __restrict__ src,
                             __nv_bfloat16* __restrict__ dst, int n8)
{
    int i = blockIdx.x * blockDim.x + threadIdx.x;
    if (i >= n8) return;
    const float4* s = (const float4*)src + (size_t)i * 2;
    float4 v0 = s[0], v1 = s[1];
    __nv_bfloat162 r0 = __float22bfloat162_rn(make_float2(v0.x, v0.y));
    __nv_bfloat162 r1 = __float22bfloat162_rn(make_float2(v0.z, v0.w));
    __nv_bfloat162 r2 = __float22bfloat162_rn(make_float2(v1.x, v1.y));
    __nv_bfloat162 r3 = __float22bfloat162_rn(make_float2(v1.z, v1.w));
    uint4 o;
    o.x = *(uint32_t*)&r0; o.y = *(uint32_t*)&r1;
    o.z = *(uint32_t*)&r2; o.w = *(uint32_t*)&r3;
    ((uint4*)dst)[i] = o;
}

// ============================================================================
// BIG fp32 GEMM (R6/R9 version, best measured): 256 thr, BM=256, BN=128,
// 16x8/thread, FFMA2, double-buffered smem. Exact ascending-k numerics.
// ============================================================================
template<int RELU>
__global__ __launch_bounds__(256, 1)
void gemm_big(const float* __restrict__ A, const float* __restrict__ Bm,
              const float* __restrict__ bias, float* __restrict__ C,
              int N, int K)
{
    __shared__ float As[2][BK][256];
    __shared__ float Bs[2][BK][128];

    int tid = threadIdx.x;
    int tr = tid >> 4;
    int tc = tid & 15;
    int row0 = blockIdx.y * 256;
    int col0 = blockIdx.x * 128;

    const float* Arow = A + (size_t)(row0 + tid) * K;
    int bk = tid >> 4;
    int bn = (tid & 15) * 8;
    int gbn = col0 + bn;

    uint64_t acc2[8][8];
    #pragma unroll
    for (int p = 0; p < 8; p++)
        #pragma unroll
        for (int j = 0; j < 8; j++) acc2[p][j] = 0ull;

    int nt = (K + BK - 1) / BK;
    const float4 f40 = make_float4(0.f, 0.f, 0.f, 0.f);
    float4 a0, a1, a2, a3, b0, b1;

    a0 = (4  <= K) ? *(const float4*)(Arow)      : f40;
    a1 = (8  <= K) ? *(const float4*)(Arow + 4)  : f40;
    a2 = (12 <= K) ? *(const float4*)(Arow + 8)  : f40;
    a3 = (16 <= K) ? *(const float4*)(Arow + 12) : f40;
    b0 = (bk < K && gbn + 4 <= N) ? *(const float4*)(Bm + (size_t)bk * N + gbn)     : f40;
    b1 = (bk < K && gbn + 8 <= N) ? *(const float4*)(Bm + (size_t)bk * N + gbn + 4) : f40;
    As[0][0][tid] = a0.x;  As[0][1][tid] = a0.y;  As[0][2][tid] = a0.z;  As[0][3][tid] = a0.w;
    As[0][4][tid] = a1.x;  As[0][5][tid] = a1.y;  As[0][6][tid] = a1.z;  As[0][7][tid] = a1.w;
    As[0][8][tid] = a2.x;  As[0][9][tid] = a2.y;  As[0][10][tid] = a2.z; As[0][11][tid] = a2.w;
    As[0][12][tid] = a3.x; As[0][13][tid] = a3.y; As[0][14][tid] = a3.z; As[0][15][tid] = a3.w;
    *(float4*)(&Bs[0][bk][bn])     = b0;
    *(float4*)(&Bs[0][bk][bn + 4]) = b1;
    __syncthreads();

    for (int t = 0; t < nt; t++) {
        int cur = t & 1;
        int kn = (t + 1) * BK;
        bool more = (t + 1 < nt);
        if (more) {
            a0 = (kn + 4  <= K) ? *(const float4*)(Arow + kn)      : f40;
            a1 = (kn + 8  <= K) ? *(const float4*)(Arow + kn + 4)  : f40;
            a2 = (kn + 12 <= K) ? *(const float4*)(Arow + kn + 8)  : f40;
            a3 = (kn + 16 <= K) ? *(const float4*)(Arow + kn + 12) : f40;
            int gk = kn + bk;
            b0 = (gk < K && gbn + 4 <= N) ? *(const float4*)(Bm + (size_t)gk * N + gbn)     : f40;
            b1 = (gk < K && gbn + 8 <= N) ? *(const float4*)(Bm + (size_t)gk * N + gbn + 4) : f40;
        }

        #pragma unroll
        for (int kk = 0; kk < BK; kk++) {
            const float* as = &As[cur][kk][tr * 16];
            ulonglong2 v0 = *(const ulonglong2*)(as);
            ulonglong2 v1 = *(const ulonglong2*)(as + 4);
            ulonglong2 v2 = *(const ulonglong2*)(as + 8);
            ulonglong2 v3 = *(const ulonglong2*)(as + 12);
            uint64_t ap[8] = {v0.x, v0.y, v1.x, v1.y, v2.x, v2.y, v3.x, v3.y};
            float4 B0 = *(const float4*)(&Bs[cur][kk][tc * 8]);
            float4 B1 = *(const float4*)(&Bs[cur][kk][tc * 8 + 4]);
            uint64_t bd[8];
            bd[0] = pack_dup(B0.x); bd[1] = pack_dup(B0.y);
            bd[2] = pack_dup(B0.z); bd[3] = pack_dup(B0.w);
            bd[4] = pack_dup(B1.x); bd[5] = pack_dup(B1.y);
            bd[6] = pack_dup(B1.z); bd[7] = pack_dup(B1.w);
            #pragma unroll
            for (int p = 0; p < 8; p++)
                #pragma unroll
                for (int j = 0; j < 8; j++)
                    ffma2(acc2[p][j], ap[p], bd[j]);
        }

        if (more) {
            int nx = cur ^ 1;
            As[nx][0][tid] = a0.x;  As[nx][1][tid] = a0.y;  As[nx][2][tid] = a0.z;  As[nx][3][tid] = a0.w;
            As[nx][4][tid] = a1.x;  As[nx][5][tid] = a1.y;  As[nx][6][tid] = a1.z;  As[nx][7][tid] = a1.w;
            As[nx][8][tid] = a2.x;  As[nx][9][tid] = a2.y;  As[nx][10][tid] = a2.z; As[nx][11][tid] = a2.w;
            As[nx][12][tid] = a3.x; As[nx][13][tid] = a3.y; As[nx][14][tid] = a3.z; As[nx][15][tid] = a3.w;
            *(float4*)(&Bs[nx][bk][bn])     = b0;
            *(float4*)(&Bs[nx][bk][bn + 4]) = b1;
        }
        __syncthreads();
    }

    float bb[8];
    #pragma unroll
    for (int j = 0; j < 8; j++) {
        int c = col0 + tc * 8 + j;
        bb[j] = (c < N) ? bias[c] : 0.f;
    }
    int c0 = col0 + tc * 8;
    #pragma unroll
    for (int p = 0; p < 8; p++) {
        #pragma unroll
        for (int half = 0; half < 2; half++) {
            int r = row0 + tr * 16 + p * 2 + half;
            float v[8];
            #pragma unroll
            for (int j = 0; j < 8; j++) {
                float2 u = unpack2(acc2[p][j]);
                float tv = __fadd_rn(half ? u.y : u.x, bb[j]);
                if (RELU) tv = fmaxf(tv, 0.f);
                v[j] = tv;
            }
            if (c0 + 4 <= N)
                *(float4*)(C + (size_t)r * N + c0)     = make_float4(v[0], v[1], v[2], v[3]);
            if (c0 + 8 <= N)
                *(float4*)(C + (size_t)r * N + c0 + 4) = make_float4(v[4], v[5], v[6], v[7]);
        }
    }
}

// ============================================================================
// SMALL fp32 GEMM: 128x128 block, 8x8 per thread, FFMA2. (enc1/enc2/dec2)
// ============================================================================
template<int RELU, int HAS_BIAS>
__global__ __launch_bounds__(256, 2)
void gemm_small(const float* __restrict__ A, const float* __restrict__ Bm,
                const float* __restrict__ bias, float* __restrict__ C,
                int N, int K, int ldc)
{
    __shared__ float As[BK][132];
    __shared__ float Bs[BK][128];

    int tid = threadIdx.x;
    int tr = tid >> 4;
    int tc = tid & 15;
    int row0 = blockIdx.y * 128;
    int col0 = blockIdx.x * 128;

    uint64_t acc2[4][8];
    #pragma unroll
    for (int p = 0; p < 4; p++)
        #pragma unroll
        for (int j = 0; j < 8; j++) acc2[p][j] = 0ull;

    for (int k0 = 0; k0 < K; k0 += BK) {
        #pragma unroll
        for (int e = 0; e < 8; e++) {
            int l = tid + e * 256;
            int m = l >> 4;
            int k = l & 15;
            int gk = k0 + k;
            float v = 0.f;
            if (gk < K) v = A[(size_t)(row0 + m) * K + gk];
            As[k][m] = v;
        }
        #pragma unroll
        for (int e = 0; e < 8; e++) {
            int l = tid + e * 256;
            int k = l >> 7;
            int n = l & 127;
            int gk = k0 + k, gn = col0 + n;
            float v = 0.f;
            if (gk < K && gn < N) v = Bm[(size_t)gk * N + gn];
            Bs[k][n] = v;
        }
        __syncthreads();

        #pragma unroll
        for (int kk = 0; kk < BK; kk++) {
            ulonglong2 va0 = *(const ulonglong2*)(&As[kk][tr * 8]);
            ulonglong2 va1 = *(const ulonglong2*)(&As[kk][tr * 8 + 4]);
            uint64_t ap[4] = {va0.x, va0.y, va1.x, va1.y};
            float4 b0 = *(const float4*)(&Bs[kk][tc * 8]);
            float4 b1 = *(const float4*)(&Bs[kk][tc * 8 + 4]);
            uint64_t bd[8];
            bd[0] = pack_dup(b0.x); bd[1] = pack_dup(b0.y);
            bd[2] = pack_dup(b0.z); bd[3] = pack_dup(b0.w);
            bd[4] = pack_dup(b1.x); bd[5] = pack_dup(b1.y);
            bd[6] = pack_dup(b1.z); bd[7] = pack_dup(b1.w);
            #pragma unroll
            for (int p = 0; p < 4; p++)
                #pragma unroll
                for (int j = 0; j < 8; j++)
                    ffma2(acc2[p][j], ap[p], bd[j]);
        }
        __syncthreads();
    }

    #pragma unroll
    for (int p = 0; p < 4; p++) {
        #pragma unroll
        for (int half = 0; half < 2; half++) {
            int r = row0 + tr * 8 + p * 2 + half;
            #pragma unroll
            for (int j = 0; j < 8; j++) {
                int c = col0 + tc * 8 + j;
                if (c < N) {
                    float2 u = unpack2(acc2[p][j]);
                    float v = half ? u.y : u.x;
                    if (HAS_BIAS) v = __fadd_rn(v, bias[c]);
                    if (RELU) v = fmaxf(v, 0.f);
                    C[(size_t)r * ldc + c] = v;
                }
            }
        }
    }
}

// ============================================================================
// Decoder table: T[s][c][n] = sum_k cb[c][k] * dec_w1[(s*512+k)*500 + n]
// ============================================================================
__global__ __launch_bounds__(256, 2)
void table_gemm(const float* __restrict__ cb, const float* __restrict__ dw1,
                float* __restrict__ table)
{
    const float* A = cb;
    const float* Bm = dw1 + (size_t)blockIdx.z * CDIM * HDIM;
    float* C = table + (size_t)blockIdx.z * CDIM * 512;

    __shared__ float As[BK][132];
    __shared__ float Bs[BK][128];

    int tid = threadIdx.x;
    int tr = tid >> 4;
    int tc = tid & 15;
    int row0 = blockIdx.y * 128;
    int col0 = blockIdx.x * 128;

    uint64_t acc2[4][8];
    #pragma unroll
    for (int p = 0; p < 4; p++)
        #pragma unroll
        for (int j = 0; j < 8; j++) acc2[p][j] = 0ull;

    for (int k0 = 0; k0 < CDIM; k0 += BK) {
        #pragma unroll
        for (int e = 0; e < 8; e++) {
            int l = tid + e * 256;
            int m = l >> 4;
            int k = l & 15;
            As[k][m] = A[(size_t)(row0 + m) * CDIM + k0 + k];
        }
        #pragma unroll
        for (int e = 0; e < 8; e++) {
            int l = tid + e * 256;
            int k = l >> 7;
            int n = l & 127;
            int gn = col0 + n;
            Bs[k][n] = (gn < HDIM) ? Bm[(size_t)(k0 + k) * HDIM + gn] : 0.f;
        }
        __syncthreads();

        #pragma unroll
        for (int kk = 0; kk < BK; kk++) {
            ulonglong2 va0 = *(const ulonglong2*)(&As[kk][tr * 8]);
            ulonglong2 va1 = *(const ulonglong2*)(&As[kk][tr * 8 + 4]);
            uint64_t ap[4] = {va0.x, va0.y, va1.x, va1.y};
            float4 b0 = *(const float4*)(&Bs[kk][tc * 8]);
            float4 b1 = *(const float4*)(&Bs[kk][tc * 8 + 4]);
            uint64_t bd[8];
            bd[0] = pack_dup(b0.x); bd[1] = pack_dup(b0.y);
            bd[2] = pack_dup(b0.z); bd[3] = pack_dup(b0.w);
            bd[4] = pack_dup(b1.x); bd[5] = pack_dup(b1.y);
            bd[6] = pack_dup(b1.z); bd[7] = pack_dup(b1.w);
            #pragma unroll
            for (int p = 0; p < 4; p++)
                #pragma unroll
                for (int j = 0; j < 8; j++)
                    ffma2(acc2[p][j], ap[p], bd[j]);
        }
        __syncthreads();
    }

    #pragma unroll
    for (int p = 0; p < 4; p++) {
        #pragma unroll
        for (int half = 0; half < 2; half++) {
            int r = row0 + tr * 8 + p * 2 + half;
            #pragma unroll
            for (int j = 0; j < 8; j++) {
                int c = col0 + tc * 8 + j;
                if (c < HDIM) {
                    float2 u = unpack2(acc2[p][j]);
                    C[(size_t)r * 512 + c] = half ? u.y : u.x;
                }
            }
        }
    }
}

// ============================================================================
// dec1 via table gather-sum
// ============================================================================
__global__ __launch_bounds__(256, 8)
void dec1_gather(const int* __restrict__ codes, const float* __restrict__ table,
                 const float* __restrict__ db1, float* __restrict__ h1)
{
    int b = blockIdx.x * 2 + (threadIdx.x >> 7);
    int t = threadIdx.x & 127;

    __shared__ int cds[2][16];
    if ((threadIdx.x & 127) < 16)
        cds[threadIdx.x >> 7][threadIdx.x & 127] = codes[b * 16 + (threadIdx.x & 127)];
    __syncthreads();

    if (t >= 125) return;
    const int* cd = cds[threadIdx.x >> 7];

    float4 acc = *(const float4*)(db1 + t * 4);
    #pragma unroll
    for (int s = 0; s < 16; s++) {
        const float4* row = (const float4*)(table + (((size_t)s * CDIM + cd[s]) << 9));
        float4 v = row[t];
        acc.x += v.x; acc.y += v.y; acc.z += v.z; acc.w += v.w;
    }
    acc.x = fmaxf(acc.x, 0.f); acc.y = fmaxf(acc.y, 0.f);
    acc.z = fmaxf(acc.z, 0.f); acc.w = fmaxf(acc.w, 0.f);
    *(float4*)(h1 + (size_t)b * HDIM + t * 4) = acc;
}

// ============================================================================
// VQ approx pass: S[r][j] = obs_bf16[r] . cb_bf16[j] via mma.sync m16n8k16.
// CTA tile: 128 rows x 128 codes, BK=32, 8 warps (4 row-groups x 2 col-groups).
// ============================================================================
#define S_LD 40   // bf16 units per smem row (32 + 8 pad -> conflict-free frags)

__global__ __launch_bounds__(256, 1)
void vq_mma(const __nv_bfloat16* __restrict__ obs_bf,
            const __nv_bfloat16* __restrict__ cb_bf,
            float* __restrict__ S)
{
    __shared__ __nv_bfloat16 As[2][128 * S_LD];
    __shared__ __nv_bfloat16 Bs[2][128 * S_LD];

    int tid  = threadIdx.x;
    int lane = tid & 31;
    int wid  = tid >> 5;
    int g    = lane >> 2;          // 0..7
    int tg   = lane & 3;           // 0..3
    int wm   = (wid >> 1) * 32;    // warp row offset
    int wn   = (wid & 1) * 64;     // warp col offset
    int row0 = blockIdx.y * 128;
    int col0 = blockIdx.x * 128;

    int lrow  = tid >> 1;          // 0..127
    int lhalf = (tid & 1) * 16;    // 0 or 16 (bf16 units)
    const uint4* gA = (const uint4*)(obs_bf + (size_t)(row0 + lrow) * CDIM + lhalf);
    const uint4* gB = (const uint4*)(cb_bf  + (size_t)(col0 + lrow) * CDIM + lhalf);

    float acc[2][8][4];
    #pragma unroll
    for (int mc = 0; mc < 2; mc++)
        #pragma unroll
        for (int nc = 0; nc < 8; nc++)
            #pragma unroll
            for (int q = 0; q < 4; q++) acc[mc][nc][q] = 0.f;

    // commit tile 0
    {
        uint4 pa0 = gA[0], pa1 = gA[1], pb0 = gB[0], pb1 = gB[1];
        uint2* pA = (uint2*)(&As[0][lrow * S_LD + lhalf]);
        pA[0] = make_uint2(pa0.x, pa0.y); pA[1] = make_uint2(pa0.z, pa0.w);
        pA[2] = make_uint2(pa1.x, pa1.y); pA[3] = make_uint2(pa1.z, pa1.w);
        uint2* pB = (uint2*)(&Bs[0][lrow * S_LD + lhalf]);
        pB[0] = make_uint2(pb0.x, pb0.y); pB[1] = make_uint2(pb0.z, pb0.w);
        pB[2] = make_uint2(pb1.x, pb1.y); pB[3] = make_uint2(pb1.z, pb1.w);
    }
    __syncthreads();

    const int NT = CDIM / 32;   // 16 k-tiles
    uint4 pa0, pa1, pb0, pb1;
    for (int t = 0; t < NT; t++) {
        int cur = t & 1;
        bool more = (t + 1 < NT);
        if (more) {
            pa0 = gA[(t + 1) * 4]; pa1 = gA[(t + 1) * 4 + 1];
            pb0 = gB[(t + 1) * 4]; pb1 = gB[(t + 1) * 4 + 1];
        }

        #pragma unroll
        for (int kk0 = 0; kk0 < 32; kk0 += 16) {
            uint32_t afr[2][4];
            #pragma unroll
            for (int mc = 0; mc < 2; mc++) {
                const __nv_bfloat16* ab = &As[cur][(wm + mc * 16 + g) * S_LD + kk0 + 2 * tg];
                afr[mc][0] = *(const uint32_t*)(ab);
                afr[mc][1] = *(const uint32_t*)(ab + 8 * S_LD);
                afr[mc][2] = *(const uint32_t*)(ab + 8);
                afr[mc][3] = *(const uint32_t*)(ab + 8 * S_LD + 8);
            }
            #pragma unroll
            for (int nc = 0; nc < 8; nc++) {
                const __nv_bfloat16* bb = &Bs[cur][(wn + nc * 8 + g) * S_LD + kk0 + 2 * tg];
                uint32_t b0 = *(const uint32_t*)(bb);
                uint32_t b1 = *(const uint32_t*)(bb + 8);
                mma_bf16(acc[0][nc], afr[0], b0, b1);
                mma_bf16(acc[1][nc], afr[1], b0, b1);
            }
        }

        if (more) {
            int nx = cur ^ 1;
            uint2* pA = (uint2*)(&As[nx][lrow * S_LD + lhalf]);
            pA[0] = make_uint2(pa0.x, pa0.y); pA[1] = make_uint2(pa0.z, pa0.w);
            pA[2] = make_uint2(pa1.x, pa1.y); pA[3] = make_uint2(pa1.z, pa1.w);
            uint2* pB = (uint2*)(&Bs[nx][lrow * S_LD + lhalf]);
            pB[0] = make_uint2(pb0.x, pb0.y); pB[1] = make_uint2(pb0.z, pb0.w);
            pB[2] = make_uint2(pb1.x, pb1.y); pB[3] = make_uint2(pb1.z, pb1.w);
        }
        __syncthreads();
    }

    // write S
    #pragma unroll
    for (int mc = 0; mc < 2; mc++) {
        #pragma unroll
        for (int nc = 0; nc < 8; nc++) {
            int r = row0 + wm + mc * 16 + g;
            int c = col0 + wn + nc * 8 + 2 * tg;
            *(float2*)(S + (size_t)r * CDIM + c)       = make_float2(acc[mc][nc][0], acc[mc][nc][1]);
            *(float2*)(S + (size_t)(r + 8) * CDIM + c) = make_float2(acc[mc][nc][2], acc[mc][nc][3]);
        }
    }
}

// ============================================================================
// VQ rescue: one warp per row. Candidates within BAND of approx min get an
// EXACT recomputation (scalar ascending-k fp32 fmaf + reference d2 op order,
// identical to the previously-passing exact kernel -> codes unchanged).
// ============================================================================
#define VQ_BAND 0.05f

__global__ __launch_bounds__(256, 4)
void vq_rescue(const float* __restrict__ S, const float* __restrict__ obs,
               const float* __restrict__ cb, const float* __restrict__ cnorm,
               const float* __restrict__ rownorm, int* __restrict__ codes)
{
    int warp = (blockIdx.x * blockDim.x + threadIdx.x) >> 5;
    int lane = threadIdx.x & 31;
    const float* Srow = S + (size_t)warp * CDIM;

    // pass 1: approx distances + warp min
    float dv[16];
    float dmin = 3.4e38f;
    #pragma unroll
    for (int i = 0; i < 16; i++) {
        int j = lane + i * 32;
        float d = cnorm[j] - 2.0f * Srow[j];
        dv[i] = d;
        dmin = fminf(dmin, d);
    }
    #pragma unroll
    for (int o = 16; o > 0; o >>= 1)
        dmin = fminf(dmin, __shfl_xor_sync(0xffffffffu, dmin, o));
    float thresh = dmin + VQ_BAND;

    // pass 2: exact recompute for candidates (lane-parallel)
    float An = rownorm[warp];
    const float* orow = obs + (size_t)warp * CDIM;
    float bestd = 3.4e38f;
    int   besti = CDIM;
    #pragma unroll 1
    for (int i = 0; i < 16; i++) {
        if (__any_sync(0xffffffffu, dv[i] <= thresh)) {
            if (dv[i] <= thresh) {
                int j = lane + i * 32;
                const float* crow = cb + (size_t)j * CDIM;
                float acc = 0.f;
                #pragma unroll 8
                for (int k = 0; k < CDIM; k++)
                    acc = fmaf(orow[k], crow[k], acc);
                float twob = __fmul_rn(2.0f, acc);
                float t2   = __fadd_rn(An, -twob);
                float d    = __fadd_rn(t2, cnorm[j]);
                if (d < bestd || (d == bestd && j < besti)) { bestd = d; besti = j; }
            }
        }
    }
    // warp reduce with lowest-index tie rule
    #pragma unroll
    for (int o = 16; o > 0; o >>= 1) {
        float od = __shfl_xor_sync(0xffffffffu, bestd, o);
        int   oi = __shfl_xor_sync(0xffffffffu, besti, o);
        if (od < bestd || (od == bestd && oi < besti)) { bestd = od; besti = oi; }
    }
    if (lane == 0) codes[warp] = besti;
}

// ============================================================================
// latent[row] = codebook[codes[row]]
// ============================================================================
__global__ void gather_latent_kernel(const int* __restrict__ codes,
                                     const float* __restrict__ cb,
                                     float* __restrict__ latent)
{
    int row  = blockIdx.x * 2 + (threadIdx.x >> 7);
    int lane = threadIdx.x & 127;
    int c = codes[row];
    const float4* src = (const float4*)(cb + (size_t)c * CDIM);
    float4* dst = (float4*)(latent + (size_t)row * CDIM);
    dst[lane] = src[lane];
}

// ============================================================================
// launch
// ============================================================================
extern "C" void kernel_launch(void* const* d_in, const int* in_sizes, int n_in,
                              void* d_out, int out_size)
{
    const float* x    = (const float*)d_in[0];
    const float* ew1  = (const float*)d_in[1];
    const float* eb1  = (const float*)d_in[2];
    const float* ew2  = (const float*)d_in[3];
    const float* eb2  = (const float*)d_in[4];
    const float* ew3  = (const float*)d_in[5];
    const float* eb3  = (const float*)d_in[6];
    const float* cb   = (const float*)d_in[7];
    const float* dw1  = (const float*)d_in[8];
    const float* db1  = (const float*)d_in[9];
    const float* dw2  = (const float*)d_in[10];
    const float* db2  = (const float*)d_in[11];

    float* out        = (float*)d_out;
    float* out_recon  = out;                                     // [8192, 784]
    float* out_obs    = out + (size_t)BROWS * DDIM;              // [131072, 512]
    float* out_latent = out_obs + (size_t)BROWS * CSDIM;         // [131072, 512]

    float *h1, *h2, *cn, *rn, *tbl, *Sbuf; int *codes;
    __nv_bfloat16 *obsbf, *cbbf;
    cudaGetSymbolAddress((void**)&h1, g_h1);
    cudaGetSymbolAddress((void**)&h2, g_h2);
    cudaGetSymbolAddress((void**)&cn, g_cnorm);
    cudaGetSymbolAddress((void**)&rn, g_rownorm);
    cudaGetSymbolAddress((void**)&tbl, g_table);
    cudaGetSymbolAddress((void**)&Sbuf, g_S);
    cudaGetSymbolAddress((void**)&obsbf, g_obsbf);
    cudaGetSymbolAddress((void**)&cbbf, g_cbbf);
    cudaGetSymbolAddress((void**)&codes, g_codes);

    // codebook-derived preprocessing (independent of encoder chain)
    cnorm_kernel<<<CDIM / 8, 256>>>(cb, cn);
    convert_bf16<<<(CDIM * CDIM / 8) / 256, 256>>>(cb, cbbf, CDIM * CDIM / 8);
    table_gemm<<<dim3(4, 4, SDIM), 256>>>(cb, dw1, tbl);

    // encoder
    gemm_small<1,1><<<dim3(4, 64), 256>>>(x,  ew1, eb1, h1, HDIM, DDIM, HDIM);
    gemm_small<1,1><<<dim3(4, 64), 256>>>(h1, ew2, eb2, h2, HDIM, HDIM, HDIM);
    gemm_big<0><<<dim3(64, 32), 256>>>(h2, ew3, eb3, out_obs, CSDIM, HDIM);

    // VQ: norms + bf16 approx GEMM (tensor cores) + exact rescue
    rownorm_kernel<<<NROWS2 / 8, 256>>>(out_obs, rn);
    convert_bf16<<<((size_t)NROWS2 * CDIM / 8) / 256, 256>>>(out_obs, obsbf,
                                                             (int)((size_t)NROWS2 * CDIM / 8));
    vq_mma<<<dim3(CDIM / 128, NROWS2 / 128), 256>>>(obsbf, cbbf, Sbuf);
    vq_rescue<<<NROWS2 / 8, 256>>>(Sbuf, out_obs, cb, cn, rn, codes);
    gather_latent_kernel<<<NROWS2 / 2, 256>>>(codes, cb, out_latent);

    // decoder
    dec1_gather<<<BROWS / 2, 256>>>(codes, tbl, db1, h1);
    gemm_small<0,1><<<dim3(7, 64), 256>>>(h1, dw2, db2, out_recon, DDIM, HDIM, DDIM);
}

// round 11
// speedup vs baseline: 5.2063x; 5.2063x over previous
#include <cuda_runtime.h>
#include <cuda_bf16.h>
#include <cstdint>

// Problem dims (fixed by the dataset)
#define BROWS 8192
#define DDIM  784
#define HDIM  500
#define CDIM  512
#define SDIM  16
#define CSDIM (CDIM * SDIM)      // 8192
#define NROWS2 (BROWS * SDIM)    // 131072
#define BK 16

// -------- scratch (no allocations allowed) ----
__device__ float g_h1[BROWS * HDIM];
__device__ float g_h2[BROWS * HDIM];
__device__ float g_cnorm[CDIM];
__device__ float g_rownorm[NROWS2];
__device__ int   g_codes[NROWS2];
__device__ float g_table[SDIM * CDIM * 512];               // 16.8 MB
__device__ float g_S[(size_t)NROWS2 * CDIM];               // approx dots, 268 MB
__device__ __nv_bfloat16 g_obs_hi[(size_t)NROWS2 * CDIM];  // 134 MB
__device__ __nv_bfloat16 g_obs_lo[(size_t)NROWS2 * CDIM];  // 134 MB
__device__ __nv_bfloat16 g_cb_hi[CDIM * CDIM];
__device__ __nv_bfloat16 g_cb_lo[CDIM * CDIM];

// ---------------- packed f32x2 helpers (sm_100+: fma.rn.f32x2) ----------------
__device__ __forceinline__ uint64_t pack_dup(float x) {
    uint64_t r;
    asm("mov.b64 %0, {%1, %1};" : "=l"(r) : "f"(x));
    return r;
}
__device__ __forceinline__ void ffma2(uint64_t& d, uint64_t a, uint64_t b) {
    asm("fma.rn.f32x2 %0, %1, %2, %0;" : "+l"(d) : "l"(a), "l"(b));
}
__device__ __forceinline__ float2 unpack2(uint64_t v) {
    float lo, hi;
    asm("mov.b64 {%0, %1}, %2;" : "=f"(lo), "=f"(hi) : "l"(v));
    return make_float2(lo, hi);
}

// ---------------- bf16 mma helper (m16n8k16, row.col, f32 acc) ----------------
__device__ __forceinline__ void mma_bf16(float* d, const uint32_t* a,
                                         uint32_t b0, uint32_t b1) {
    asm volatile(
        "mma.sync.aligned.m16n8k16.row.col.f32.bf16.bf16.f32 "
        "{%0,%1,%2,%3}, {%4,%5,%6,%7}, {%8,%9}, {%0,%1,%2,%3};"
        : "+f"(d[0]), "+f"(d[1]), "+f"(d[2]), "+f"(d[3])
        : "r"(a[0]), "r"(a[1]), "r"(a[2]), "r"(a[3]), "r"(b0), "r"(b1));
}

// ============================================================================
// Codebook / obs row norms in DOUBLE (one warp per row)
// ============================================================================
__global__ void cnorm_kernel(const float* __restrict__ cb, float* __restrict__ cn) {
    int warp = (blockIdx.x * blockDim.x + threadIdx.x) >> 5;
    int lane = threadIdx.x & 31;
    if (warp >= CDIM) return;
    const float* row = cb + (size_t)warp * CDIM;
    double s = 0.0;
    for (int k = lane; k < CDIM; k += 32) { double v = (double)row[k]; s += v * v; }
    #pragma unroll
    for (int o = 16; o > 0; o >>= 1) s += __shfl_down_sync(0xffffffffu, s, o);
    if (lane == 0) cn[warp] = (float)s;
}

__global__ void rownorm_kernel(const float* __restrict__ obs, float* __restrict__ rn) {
    int warp = (blockIdx.x * blockDim.x + threadIdx.x) >> 5;
    int lane = threadIdx.x & 31;
    if (warp >= NROWS2) return;
    const float* row = obs + (size_t)warp * CDIM;
    double s = 0.0;
    for (int k = lane; k < CDIM; k += 32) { double v = (double)row[k]; s += v * v; }
    #pragma unroll
    for (int o = 16; o > 0; o >>= 1) s += __shfl_down_sync(0xffffffffu, s, o);
    if (lane == 0) rn[warp] = (float)s;
}

// ============================================================================
// fp32 -> split bf16 (hi + lo): hi = bf16(v), lo = bf16(v - hi)
// 8 elements per thread.
// ============================================================================
__global__ void convert_split(const float* __restrict__ src,
                              __nv_bfloat16* __restrict__ hi,
                              __nv_bfloat16* __restrict__ lo, int n8)
{
    int i = blockIdx.x * blockDim.x + threadIdx.x;
    if (i >= n8) return;
    const float4* s = (const float4*)src + (size_t)i * 2;
    float4 v0 = s[0], v1 = s[1];
    float v[8] = {v0.x, v0.y, v0.z, v0.w, v1.x, v1.y, v1.z, v1.w};
    __nv_bfloat16 h[8], l[8];
    #pragma unroll
    for (int e = 0; e < 8; e++) {
        h[e] = __float2bfloat16_rn(v[e]);
        l[e] = __float2bfloat16_rn(v[e] - __bfloat162float(h[e]));
    }
    uint4 oh, ol;
    oh.x = *(uint32_t*)&h[0]; oh.y = *(uint32_t*)&h[2];
    oh.z = *(uint32_t*)&h[4]; oh.w = *(uint32_t*)&h[6];
    ol.x = *(uint32_t*)&l[0]; ol.y = *(uint32_t*)&l[2];
    ol.z = *(uint32_t*)&l[4]; ol.w = *(uint32_t*)&l[6];
    ((uint4*)hi)[i] = oh;
    ((uint4*)lo)[i] = ol;
}

// ============================================================================
// BIG fp32 GEMM (R6/R9 version, best measured): 256 thr, BM=256, BN=128,
// 16x8/thread, FFMA2, double-buffered smem. Exact ascending-k numerics.
// ============================================================================
template<int RELU>
__global__ __launch_bounds__(256, 1)
void gemm_big(const float* __restrict__ A, const float* __restrict__ Bm,
              const float* __restrict__ bias, float* __restrict__ C,
              int N, int K)
{
    __shared__ float As[2][BK][256];
    __shared__ float Bs[2][BK][128];

    int tid = threadIdx.x;
    int tr = tid >> 4;
    int tc = tid & 15;
    int row0 = blockIdx.y * 256;
    int col0 = blockIdx.x * 128;

    const float* Arow = A + (size_t)(row0 + tid) * K;
    int bk = tid >> 4;
    int bn = (tid & 15) * 8;
    int gbn = col0 + bn;

    uint64_t acc2[8][8];
    #pragma unroll
    for (int p = 0; p < 8; p++)
        #pragma unroll
        for (int j = 0; j < 8; j++) acc2[p][j] = 0ull;

    int nt = (K + BK - 1) / BK;
    const float4 f40 = make_float4(0.f, 0.f, 0.f, 0.f);
    float4 a0, a1, a2, a3, b0, b1;

    a0 = (4  <= K) ? *(const float4*)(Arow)      : f40;
    a1 = (8  <= K) ? *(const float4*)(Arow + 4)  : f40;
    a2 = (12 <= K) ? *(const float4*)(Arow + 8)  : f40;
    a3 = (16 <= K) ? *(const float4*)(Arow + 12) : f40;
    b0 = (bk < K && gbn + 4 <= N) ? *(const float4*)(Bm + (size_t)bk * N + gbn)     : f40;
    b1 = (bk < K && gbn + 8 <= N) ? *(const float4*)(Bm + (size_t)bk * N + gbn + 4) : f40;
    As[0][0][tid] = a0.x;  As[0][1][tid] = a0.y;  As[0][2][tid] = a0.z;  As[0][3][tid] = a0.w;
    As[0][4][tid] = a1.x;  As[0][5][tid] = a1.y;  As[0][6][tid] = a1.z;  As[0][7][tid] = a1.w;
    As[0][8][tid] = a2.x;  As[0][9][tid] = a2.y;  As[0][10][tid] = a2.z; As[0][11][tid] = a2.w;
    As[0][12][tid] = a3.x; As[0][13][tid] = a3.y; As[0][14][tid] = a3.z; As[0][15][tid] = a3.w;
    *(float4*)(&Bs[0][bk][bn])     = b0;
    *(float4*)(&Bs[0][bk][bn + 4]) = b1;
    __syncthreads();

    for (int t = 0; t < nt; t++) {
        int cur = t & 1;
        int kn = (t + 1) * BK;
        bool more = (t + 1 < nt);
        if (more) {
            a0 = (kn + 4  <= K) ? *(const float4*)(Arow + kn)      : f40;
            a1 = (kn + 8  <= K) ? *(const float4*)(Arow + kn + 4)  : f40;
            a2 = (kn + 12 <= K) ? *(const float4*)(Arow + kn + 8)  : f40;
            a3 = (kn + 16 <= K) ? *(const float4*)(Arow + kn + 12) : f40;
            int gk = kn + bk;
            b0 = (gk < K && gbn + 4 <= N) ? *(const float4*)(Bm + (size_t)gk * N + gbn)     : f40;
            b1 = (gk < K && gbn + 8 <= N) ? *(const float4*)(Bm + (size_t)gk * N + gbn + 4) : f40;
        }

        #pragma unroll
        for (int kk = 0; kk < BK; kk++) {
            const float* as = &As[cur][kk][tr * 16];
            ulonglong2 v0 = *(const ulonglong2*)(as);
            ulonglong2 v1 = *(const ulonglong2*)(as + 4);
            ulonglong2 v2 = *(const ulonglong2*)(as + 8);
            ulonglong2 v3 = *(const ulonglong2*)(as + 12);
            uint64_t ap[8] = {v0.x, v0.y, v1.x, v1.y, v2.x, v2.y, v3.x, v3.y};
            float4 B0 = *(const float4*)(&Bs[cur][kk][tc * 8]);
            float4 B1 = *(const float4*)(&Bs[cur][kk][tc * 8 + 4]);
            uint64_t bd[8];
            bd[0] = pack_dup(B0.x); bd[1] = pack_dup(B0.y);
            bd[2] = pack_dup(B0.z); bd[3] = pack_dup(B0.w);
            bd[4] = pack_dup(B1.x); bd[5] = pack_dup(B1.y);
            bd[6] = pack_dup(B1.z); bd[7] = pack_dup(B1.w);
            #pragma unroll
            for (int p = 0; p < 8; p++)
                #pragma unroll
                for (int j = 0; j < 8; j++)
                    ffma2(acc2[p][j], ap[p], bd[j]);
        }

        if (more) {
            int nx = cur ^ 1;
            As[nx][0][tid] = a0.x;  As[nx][1][tid] = a0.y;  As[nx][2][tid] = a0.z;  As[nx][3][tid] = a0.w;
            As[nx][4][tid] = a1.x;  As[nx][5][tid] = a1.y;  As[nx][6][tid] = a1.z;  As[nx][7][tid] = a1.w;
            As[nx][8][tid] = a2.x;  As[nx][9][tid] = a2.y;  As[nx][10][tid] = a2.z; As[nx][11][tid] = a2.w;
            As[nx][12][tid] = a3.x; As[nx][13][tid] = a3.y; As[nx][14][tid] = a3.z; As[nx][15][tid] = a3.w;
            *(float4*)(&Bs[nx][bk][bn])     = b0;
            *(float4*)(&Bs[nx][bk][bn + 4]) = b1;
        }
        __syncthreads();
    }

    float bb[8];
    #pragma unroll
    for (int j = 0; j < 8; j++) {
        int c = col0 + tc * 8 + j;
        bb[j] = (c < N) ? bias[c] : 0.f;
    }
    int c0 = col0 + tc * 8;
    #pragma unroll
    for (int p = 0; p < 8; p++) {
        #pragma unroll
        for (int half = 0; half < 2; half++) {
            int r = row0 + tr * 16 + p * 2 + half;
            float v[8];
            #pragma unroll
            for (int j = 0; j < 8; j++) {
                float2 u = unpack2(acc2[p][j]);
                float tv = __fadd_rn(half ? u.y : u.x, bb[j]);
                if (RELU) tv = fmaxf(tv, 0.f);
                v[j] = tv;
            }
            if (c0 + 4 <= N)
                *(float4*)(C + (size_t)r * N + c0)     = make_float4(v[0], v[1], v[2], v[3]);
            if (c0 + 8 <= N)
                *(float4*)(C + (size_t)r * N + c0 + 4) = make_float4(v[4], v[5], v[6], v[7]);
        }
    }
}

// ============================================================================
// SMALL fp32 GEMM: 128x128 block, 8x8 per thread, FFMA2. (enc1/enc2/dec2)
// ============================================================================
template<int RELU, int HAS_BIAS>
__global__ __launch_bounds__(256, 2)
void gemm_small(const float* __restrict__ A, const float* __restrict__ Bm,
                const float* __restrict__ bias, float* __restrict__ C,
                int N, int K, int ldc)
{
    __shared__ float As[BK][132];
    __shared__ float Bs[BK][128];

    int tid = threadIdx.x;
    int tr = tid >> 4;
    int tc = tid & 15;
    int row0 = blockIdx.y * 128;
    int col0 = blockIdx.x * 128;

    uint64_t acc2[4][8];
    #pragma unroll
    for (int p = 0; p < 4; p++)
        #pragma unroll
        for (int j = 0; j < 8; j++) acc2[p][j] = 0ull;

    for (int k0 = 0; k0 < K; k0 += BK) {
        #pragma unroll
        for (int e = 0; e < 8; e++) {
            int l = tid + e * 256;
            int m = l >> 4;
            int k = l & 15;
            int gk = k0 + k;
            float v = 0.f;
            if (gk < K) v = A[(size_t)(row0 + m) * K + gk];
            As[k][m] = v;
        }
        #pragma unroll
        for (int e = 0; e < 8; e++) {
            int l = tid + e * 256;
            int k = l >> 7;
            int n = l & 127;
            int gk = k0 + k, gn = col0 + n;
            float v = 0.f;
            if (gk < K && gn < N) v = Bm[(size_t)gk * N + gn];
            Bs[k][n] = v;
        }
        __syncthreads();

        #pragma unroll
        for (int kk = 0; kk < BK; kk++) {
            ulonglong2 va0 = *(const ulonglong2*)(&As[kk][tr * 8]);
            ulonglong2 va1 = *(const ulonglong2*)(&As[kk][tr * 8 + 4]);
            uint64_t ap[4] = {va0.x, va0.y, va1.x, va1.y};
            float4 b0 = *(const float4*)(&Bs[kk][tc * 8]);
            float4 b1 = *(const float4*)(&Bs[kk][tc * 8 + 4]);
            uint64_t bd[8];
            bd[0] = pack_dup(b0.x); bd[1] = pack_dup(b0.y);
            bd[2] = pack_dup(b0.z); bd[3] = pack_dup(b0.w);
            bd[4] = pack_dup(b1.x); bd[5] = pack_dup(b1.y);
            bd[6] = pack_dup(b1.z); bd[7] = pack_dup(b1.w);
            #pragma unroll
            for (int p = 0; p < 4; p++)
                #pragma unroll
                for (int j = 0; j < 8; j++)
                    ffma2(acc2[p][j], ap[p], bd[j]);
        }
        __syncthreads();
    }

    #pragma unroll
    for (int p = 0; p < 4; p++) {
        #pragma unroll
        for (int half = 0; half < 2; half++) {
            int r = row0 + tr * 8 + p * 2 + half;
            #pragma unroll
            for (int j = 0; j < 8; j++) {
                int c = col0 + tc * 8 + j;
                if (c < N) {
                    float2 u = unpack2(acc2[p][j]);
                    float v = half ? u.y : u.x;
                    if (HAS_BIAS) v = __fadd_rn(v, bias[c]);
                    if (RELU) v = fmaxf(v, 0.f);
                    C[(size_t)r * ldc + c] = v;
                }
            }
        }
    }
}

// ============================================================================
// Decoder table: T[s][c][n] = sum_k cb[c][k] * dec_w1[(s*512+k)*500 + n]
// ============================================================================
__global__ __launch_bounds__(256, 2)
void table_gemm(const float* __restrict__ cb, const float* __restrict__ dw1,
                float* __restrict__ table)
{
    const float* A = cb;
    const float* Bm = dw1 + (size_t)blockIdx.z * CDIM * HDIM;
    float* C = table + (size_t)blockIdx.z * CDIM * 512;

    __shared__ float As[BK][132];
    __shared__ float Bs[BK][128];

    int tid = threadIdx.x;
    int tr = tid >> 4;
    int tc = tid & 15;
    int row0 = blockIdx.y * 128;
    int col0 = blockIdx.x * 128;

    uint64_t acc2[4][8];
    #pragma unroll
    for (int p = 0; p < 4; p++)
        #pragma unroll
        for (int j = 0; j < 8; j++) acc2[p][j] = 0ull;

    for (int k0 = 0; k0 < CDIM; k0 += BK) {
        #pragma unroll
        for (int e = 0; e < 8; e++) {
            int l = tid + e * 256;
            int m = l >> 4;
            int k = l & 15;
            As[k][m] = A[(size_t)(row0 + m) * CDIM + k0 + k];
        }
        #pragma unroll
        for (int e = 0; e < 8; e++) {
            int l = tid + e * 256;
            int k = l >> 7;
            int n = l & 127;
            int gn = col0 + n;
            Bs[k][n] = (gn < HDIM) ? Bm[(size_t)(k0 + k) * HDIM + gn] : 0.f;
        }
        __syncthreads();

        #pragma unroll
        for (int kk = 0; kk < BK; kk++) {
            ulonglong2 va0 = *(const ulonglong2*)(&As[kk][tr * 8]);
            ulonglong2 va1 = *(const ulonglong2*)(&As[kk][tr * 8 + 4]);
            uint64_t ap[4] = {va0.x, va0.y, va1.x, va1.y};
            float4 b0 = *(const float4*)(&Bs[kk][tc * 8]);
            float4 b1 = *(const float4*)(&Bs[kk][tc * 8 + 4]);
            uint64_t bd[8];
            bd[0] = pack_dup(b0.x); bd[1] = pack_dup(b0.y);
            bd[2] = pack_dup(b0.z); bd[3] = pack_dup(b0.w);
            bd[4] = pack_dup(b1.x); bd[5] = pack_dup(b1.y);
            bd[6] = pack_dup(b1.z); bd[7] = pack_dup(b1.w);
            #pragma unroll
            for (int p = 0; p < 4; p++)
                #pragma unroll
                for (int j = 0; j < 8; j++)
                    ffma2(acc2[p][j], ap[p], bd[j]);
        }
        __syncthreads();
    }

    #pragma unroll
    for (int p = 0; p < 4; p++) {
        #pragma unroll
        for (int half = 0; half < 2; half++) {
            int r = row0 + tr * 8 + p * 2 + half;
            #pragma unroll
            for (int j = 0; j < 8; j++) {
                int c = col0 + tc * 8 + j;
                if (c < HDIM) {
                    float2 u = unpack2(acc2[p][j]);
                    C[(size_t)r * 512 + c] = half ? u.y : u.x;
                }
            }
        }
    }
}

// ============================================================================
// dec1 via table gather-sum
// ============================================================================
__global__ __launch_bounds__(256, 8)
void dec1_gather(const int* __restrict__ codes, const float* __restrict__ table,
                 const float* __restrict__ db1, float* __restrict__ h1)
{
    int b = blockIdx.x * 2 + (threadIdx.x >> 7);
    int t = threadIdx.x & 127;

    __shared__ int cds[2][16];
    if ((threadIdx.x & 127) < 16)
        cds[threadIdx.x >> 7][threadIdx.x & 127] = codes[b * 16 + (threadIdx.x & 127)];
    __syncthreads();

    if (t >= 125) return;
    const int* cd = cds[threadIdx.x >> 7];

    float4 acc = *(const float4*)(db1 + t * 4);
    #pragma unroll
    for (int s = 0; s < 16; s++) {
        const float4* row = (const float4*)(table + (((size_t)s * CDIM + cd[s]) << 9));
        float4 v = row[t];
        acc.x += v.x; acc.y += v.y; acc.z += v.z; acc.w += v.w;
    }
    acc.x = fmaxf(acc.x, 0.f); acc.y = fmaxf(acc.y, 0.f);
    acc.z = fmaxf(acc.z, 0.f); acc.w = fmaxf(acc.w, 0.f);
    *(float4*)(h1 + (size_t)b * HDIM + t * 4) = acc;
}

// ============================================================================
// VQ approx pass, SPLIT bf16: S = hi.hi' + hi.lo' + lo.hi'  (fp32 acc).
// CTA tile: 128 rows x 128 codes, k-chunk 32, 8 warps. Single-stage smem.
// Fragment indexing identical to the R10-validated vq_mma.
// ============================================================================
#define S_LD 40   // bf16 units per smem row (32 + 8 pad)

__global__ __launch_bounds__(256)
void vq_mma3(const __nv_bfloat16* __restrict__ ah,
             const __nv_bfloat16* __restrict__ al,
             const __nv_bfloat16* __restrict__ bh,
             const __nv_bfloat16* __restrict__ bl,
             float* __restrict__ S)
{
    __shared__ __nv_bfloat16 Ah[128 * S_LD];
    __shared__ __nv_bfloat16 Al[128 * S_LD];
    __shared__ __nv_bfloat16 Bh[128 * S_LD];
    __shared__ __nv_bfloat16 Bl[128 * S_LD];

    int tid  = threadIdx.x;
    int lane = tid & 31;
    int wid  = tid >> 5;
    int g    = lane >> 2;
    int tg   = lane & 3;
    int wm   = (wid >> 1) * 32;
    int wn   = (wid & 1) * 64;
    int row0 = blockIdx.y * 128;
    int col0 = blockIdx.x * 128;

    int lrow  = tid >> 1;
    int lhalf = (tid & 1) * 16;
    const uint4* gAh = (const uint4*)(ah + (size_t)(row0 + lrow) * CDIM + lhalf);
    const uint4* gAl = (const uint4*)(al + (size_t)(row0 + lrow) * CDIM + lhalf);
    const uint4* gBh = (const uint4*)(bh + (size_t)(col0 + lrow) * CDIM + lhalf);
    const uint4* gBl = (const uint4*)(bl + (size_t)(col0 + lrow) * CDIM + lhalf);

    float acc[2][8][4];
    #pragma unroll
    for (int mc = 0; mc < 2; mc++)
        #pragma unroll
        for (int nc = 0; nc < 8; nc++)
            #pragma unroll
            for (int q = 0; q < 4; q++) acc[mc][nc][q] = 0.f;

    const int NT = CDIM / 32;   // 16 k-tiles
    for (int t = 0; t < NT; t++) {
        // load tile t (hi+lo of both operands)
        {
            uint4 va0 = gAh[t * 4], va1 = gAh[t * 4 + 1];
            uint4 wa0 = gAl[t * 4], wa1 = gAl[t * 4 + 1];
            uint4 vb0 = gBh[t * 4], vb1 = gBh[t * 4 + 1];
            uint4 wb0 = gBl[t * 4], wb1 = gBl[t * 4 + 1];
            uint2* p;
            p = (uint2*)(&Ah[lrow * S_LD + lhalf]);
            p[0] = make_uint2(va0.x, va0.y); p[1] = make_uint2(va0.z, va0.w);
            p[2] = make_uint2(va1.x, va1.y); p[3] = make_uint2(va1.z, va1.w);
            p = (uint2*)(&Al[lrow * S_LD + lhalf]);
            p[0] = make_uint2(wa0.x, wa0.y); p[1] = make_uint2(wa0.z, wa0.w);
            p[2] = make_uint2(wa1.x, wa1.y); p[3] = make_uint2(wa1.z, wa1.w);
            p = (uint2*)(&Bh[lrow * S_LD + lhalf]);
            p[0] = make_uint2(vb0.x, vb0.y); p[1] = make_uint2(vb0.z, vb0.w);
            p[2] = make_uint2(vb1.x, vb1.y); p[3] = make_uint2(vb1.z, vb1.w);
            p = (uint2*)(&Bl[lrow * S_LD + lhalf]);
            p[0] = make_uint2(wb0.x, wb0.y); p[1] = make_uint2(wb0.z, wb0.w);
            p[2] = make_uint2(wb1.x, wb1.y); p[3] = make_uint2(wb1.z, wb1.w);
        }
        __syncthreads();

        #pragma unroll
        for (int kk0 = 0; kk0 < 32; kk0 += 16) {
            uint32_t ahf[2][4], alf[2][4];
            #pragma unroll
            for (int mc = 0; mc < 2; mc++) {
                int base = (wm + mc * 16 + g) * S_LD + kk0 + 2 * tg;
                ahf[mc][0] = *(const uint32_t*)(&Ah[base]);
                ahf[mc][1] = *(const uint32_t*)(&Ah[base + 8 * S_LD]);
                ahf[mc][2] = *(const uint32_t*)(&Ah[base + 8]);
                ahf[mc][3] = *(const uint32_t*)(&Ah[base + 8 * S_LD + 8]);
                alf[mc][0] = *(const uint32_t*)(&Al[base]);
                alf[mc][1] = *(const uint32_t*)(&Al[base + 8 * S_LD]);
                alf[mc][2] = *(const uint32_t*)(&Al[base + 8]);
                alf[mc][3] = *(const uint32_t*)(&Al[base + 8 * S_LD + 8]);
            }
            #pragma unroll
            for (int nc = 0; nc < 8; nc++) {
                int bbase = (wn + nc * 8 + g) * S_LD + kk0 + 2 * tg;
                uint32_t bh0 = *(const uint32_t*)(&Bh[bbase]);
                uint32_t bh1 = *(const uint32_t*)(&Bh[bbase + 8]);
                uint32_t bl0 = *(const uint32_t*)(&Bl[bbase]);
                uint32_t bl1 = *(const uint32_t*)(&Bl[bbase + 8]);
                #pragma unroll
                for (int mc = 0; mc < 2; mc++) {
                    mma_bf16(acc[mc][nc], ahf[mc], bh0, bh1);   // hi.hi
                    mma_bf16(acc[mc][nc], ahf[mc], bl0, bl1);   // hi.lo
                    mma_bf16(acc[mc][nc], alf[mc], bh0, bh1);   // lo.hi
                }
            }
        }
        __syncthreads();
    }

    #pragma unroll
    for (int mc = 0; mc < 2; mc++) {
        #pragma unroll
        for (int nc = 0; nc < 8; nc++) {
            int r = row0 + wm + mc * 16 + g;
            int c = col0 + wn + nc * 8 + 2 * tg;
            *(float2*)(S + (size_t)r * CDIM + c)       = make_float2(acc[mc][nc][0], acc[mc][nc][1]);
            *(float2*)(S + (size_t)(r + 8) * CDIM + c) = make_float2(acc[mc][nc][2], acc[mc][nc][3]);
        }
    }
}

// ============================================================================
// VQ select: one warp per row. With split-bf16, |d_approx - d_ref| <= ~1.2e-5.
// Band 2e-4 (8x margin). If exactly ONE candidate in band -> it IS the
// reference argmin (no recompute). Else exact recompute of the few candidates
// with the validated ascending-k scalar chain + reference d2 op order.
// ============================================================================
#define VQ_BAND 2e-4f

__global__ __launch_bounds__(256, 4)
void vq_select(const float* __restrict__ S, const float* __restrict__ obs,
               const float* __restrict__ cb, const float* __restrict__ cnorm,
               const float* __restrict__ rownorm, int* __restrict__ codes)
{
    int warp = (blockIdx.x * blockDim.x + threadIdx.x) >> 5;
    int lane = threadIdx.x & 31;
    const float* Srow = S + (size_t)warp * CDIM;

    // pass 1: approx distances + warp min
    float dv[16];
    float dmin = 3.4e38f;
    #pragma unroll
    for (int i = 0; i < 16; i++) {
        int j = lane + i * 32;
        float d = cnorm[j] - 2.0f * Srow[j];
        dv[i] = d;
        dmin = fminf(dmin, d);
    }
    #pragma unroll
    for (int o = 16; o > 0; o >>= 1)
        dmin = fminf(dmin, __shfl_xor_sync(0xffffffffu, dmin, o));
    float thresh = dmin + VQ_BAND;

    // candidate census
    int cnt = 0;
    int myidx = 0x7fffffff;
    #pragma unroll
    for (int i = 0; i < 16; i++) {
        if (dv[i] <= thresh) {
            cnt++;
            int j = lane + i * 32;
            if (j < myidx) myidx = j;
        }
    }
    int total = cnt;
    int jmin = myidx;
    #pragma unroll
    for (int o = 16; o > 0; o >>= 1) {
        total += __shfl_xor_sync(0xffffffffu, total, o);
        jmin = min(jmin, __shfl_xor_sync(0xffffffffu, jmin, o));
    }

    if (total == 1) {
        if (lane == 0) codes[warp] = jmin;
        return;
    }

    // rare path: exact recompute of candidates (validated bitwise chain)
    float An = rownorm[warp];
    const float* orow = obs + (size_t)warp * CDIM;
    float bestd = 3.4e38f;
    int   besti = CDIM;
    #pragma unroll 1
    for (int i = 0; i < 16; i++) {
        if (__any_sync(0xffffffffu, dv[i] <= thresh)) {
            if (dv[i] <= thresh) {
                int j = lane + i * 32;
                const float* crow = cb + (size_t)j * CDIM;
                float acc = 0.f;
                #pragma unroll 8
                for (int k = 0; k < CDIM; k++)
                    acc = fmaf(orow[k], crow[k], acc);
                float twob = __fmul_rn(2.0f, acc);
                float t2   = __fadd_rn(An, -twob);
                float d    = __fadd_rn(t2, cnorm[j]);
                if (d < bestd || (d == bestd && j < besti)) { bestd = d; besti = j; }
            }
        }
    }
    #pragma unroll
    for (int o = 16; o > 0; o >>= 1) {
        float od = __shfl_xor_sync(0xffffffffu, bestd, o);
        int   oi = __shfl_xor_sync(0xffffffffu, besti, o);
        if (od < bestd || (od == bestd && oi < besti)) { bestd = od; besti = oi; }
    }
    if (lane == 0) codes[warp] = besti;
}

// ============================================================================
// latent[row] = codebook[codes[row]]
// ============================================================================
__global__ void gather_latent_kernel(const int* __restrict__ codes,
                                     const float* __restrict__ cb,
                                     float* __restrict__ latent)
{
    int row  = blockIdx.x * 2 + (threadIdx.x >> 7);
    int lane = threadIdx.x & 127;
    int c = codes[row];
    const float4* src = (const float4*)(cb + (size_t)c * CDIM);
    float4* dst = (float4*)(latent + (size_t)row * CDIM);
    dst[lane] = src[lane];
}

// ============================================================================
// launch
// ============================================================================
extern "C" void kernel_launch(void* const* d_in, const int* in_sizes, int n_in,
                              void* d_out, int out_size)
{
    const float* x    = (const float*)d_in[0];
    const float* ew1  = (const float*)d_in[1];
    const float* eb1  = (const float*)d_in[2];
    const float* ew2  = (const float*)d_in[3];
    const float* eb2  = (const float*)d_in[4];
    const float* ew3  = (const float*)d_in[5];
    const float* eb3  = (const float*)d_in[6];
    const float* cb   = (const float*)d_in[7];
    const float* dw1  = (const float*)d_in[8];
    const float* db1  = (const float*)d_in[9];
    const float* dw2  = (const float*)d_in[10];
    const float* db2  = (const float*)d_in[11];

    float* out        = (float*)d_out;
    float* out_recon  = out;                                     // [8192, 784]
    float* out_obs    = out + (size_t)BROWS * DDIM;              // [131072, 512]
    float* out_latent = out_obs + (size_t)BROWS * CSDIM;         // [131072, 512]

    float *h1, *h2, *cn, *rn, *tbl, *Sbuf; int *codes;
    __nv_bfloat16 *ohi, *olo, *chi, *clo;
    cudaGetSymbolAddress((void**)&h1, g_h1);
    cudaGetSymbolAddress((void**)&h2, g_h2);
    cudaGetSymbolAddress((void**)&cn, g_cnorm);
    cudaGetSymbolAddress((void**)&rn, g_rownorm);
    cudaGetSymbolAddress((void**)&tbl, g_table);
    cudaGetSymbolAddress((void**)&Sbuf, g_S);
    cudaGetSymbolAddress((void**)&ohi, g_obs_hi);
    cudaGetSymbolAddress((void**)&olo, g_obs_lo);
    cudaGetSymbolAddress((void**)&chi, g_cb_hi);
    cudaGetSymbolAddress((void**)&clo, g_cb_lo);
    cudaGetSymbolAddress((void**)&codes, g_codes);

    // codebook-derived preprocessing (independent of encoder chain)
    cnorm_kernel<<<CDIM / 8, 256>>>(cb, cn);
    convert_split<<<(CDIM * CDIM / 8) / 256, 256>>>(cb, chi, clo, CDIM * CDIM / 8);
    table_gemm<<<dim3(4, 4, SDIM), 256>>>(cb, dw1, tbl);

    // encoder
    gemm_small<1,1><<<dim3(4, 64), 256>>>(x,  ew1, eb1, h1, HDIM, DDIM, HDIM);
    gemm_small<1,1><<<dim3(4, 64), 256>>>(h1, ew2, eb2, h2, HDIM, HDIM, HDIM);
    gemm_big<0><<<dim3(64, 32), 256>>>(h2, ew3, eb3, out_obs, CSDIM, HDIM);

    // VQ: norms + split-bf16 approx GEMM (tensor cores) + band select
    rownorm_kernel<<<NROWS2 / 8, 256>>>(out_obs, rn);
    convert_split<<<(int)(((size_t)NROWS2 * CDIM / 8) / 256), 256>>>(
        out_obs, ohi, olo, (int)((size_t)NROWS2 * CDIM / 8));
    vq_mma3<<<dim3(CDIM / 128, NROWS2 / 128), 256>>>(ohi, olo, chi, clo, Sbuf);
    vq_select<<<NROWS2 / 8, 256>>>(Sbuf, out_obs, cb, cn, rn, codes);
    gather_latent_kernel<<<NROWS2 / 2, 256>>>(codes, cb, out_latent);

    // decoder
    dec1_gather<<<BROWS / 2, 256>>>(codes, tbl, db1, h1);
    gemm_small<0,1><<<dim3(7, 64), 256>>>(h1, dw2, db2, out_recon, DDIM, HDIM, DDIM);
}

// round 14
// speedup vs baseline: 6.8289x; 1.3117x over previous
#include <cuda_runtime.h>
#include <cuda_bf16.h>
#include <cstdint>

// Problem dims (fixed by the dataset)
#define BROWS 8192
#define DDIM  784
#define HDIM  500
#define CDIM  512
#define SDIM  16
#define CSDIM (CDIM * SDIM)      // 8192
#define NROWS2 (BROWS * SDIM)    // 131072
#define BK 16
#define VQ_BAND 1e-4f

// -------- scratch (no allocations allowed) ----
__device__ float g_h1[BROWS * HDIM];
__device__ float g_h2[BROWS * HDIM];
__device__ float g_cnorm[CDIM];
__device__ int   g_codes[NROWS2];
__device__ float g_table[SDIM * CDIM * 512];               // 16.8 MB
__device__ float g_S[(size_t)NROWS2 * CDIM];               // approx dots, 268 MB
__device__ __nv_bfloat16 g_obs_hi[(size_t)NROWS2 * CDIM];  // 134 MB
__device__ __nv_bfloat16 g_obs_lo[(size_t)NROWS2 * CDIM];  // 134 MB
__device__ __nv_bfloat16 g_cb_hi[CDIM * CDIM];
__device__ __nv_bfloat16 g_cb_lo[CDIM * CDIM];
__device__ __nv_bfloat16 g_h2h[BROWS * CDIM];              // h2 split, K padded 500->512
__device__ __nv_bfloat16 g_h2l[BROWS * CDIM];
__device__ __nv_bfloat16 g_w3th[(size_t)CSDIM * CDIM];     // W3^T split [n][k], 67M..134MB
__device__ __nv_bfloat16 g_w3tl[(size_t)CSDIM * CDIM];
__device__ int g_amb_rows[NROWS2];
__device__ int g_amb_count;

// ---------------- packed f32x2 helpers ----------------
__device__ __forceinline__ uint64_t pack_dup(float x) {
    uint64_t r;
    asm("mov.b64 %0, {%1, %1};" : "=l"(r) : "f"(x));
    return r;
}
__device__ __forceinline__ void ffma2(uint64_t& d, uint64_t a, uint64_t b) {
    asm("fma.rn.f32x2 %0, %1, %2, %0;" : "+l"(d) : "l"(a), "l"(b));
}
__device__ __forceinline__ float2 unpack2(uint64_t v) {
    float lo, hi;
    asm("mov.b64 {%0, %1}, %2;" : "=f"(lo), "=f"(hi) : "l"(v));
    return make_float2(lo, hi);
}

// ---------------- bf16 mma helper (m16n8k16, row.col, f32 acc) ----------------
__device__ __forceinline__ void mma_bf16(float* d, const uint32_t* a,
                                         uint32_t b0, uint32_t b1) {
    asm volatile(
        "mma.sync.aligned.m16n8k16.row.col.f32.bf16.bf16.f32 "
        "{%0,%1,%2,%3}, {%4,%5,%6,%7}, {%8,%9}, {%0,%1,%2,%3};"
        : "+f"(d[0]), "+f"(d[1]), "+f"(d[2]), "+f"(d[3])
        : "r"(a[0]), "r"(a[1]), "r"(a[2]), "r"(a[3]), "r"(b0), "r"(b1));
}

// ============================================================================
// Codebook row norms in DOUBLE (one warp per row)
// ============================================================================
__global__ void cnorm_kernel(const float* __restrict__ cb, float* __restrict__ cn) {
    int warp = (blockIdx.x * blockDim.x + threadIdx.x) >> 5;
    int lane = threadIdx.x & 31;
    if (warp >= CDIM) return;
    const float* row = cb + (size_t)warp * CDIM;
    double s = 0.0;
    for (int k = lane; k < CDIM; k += 32) { double v = (double)row[k]; s += v * v; }
    #pragma unroll
    for (int o = 16; o > 0; o >>= 1) s += __shfl_down_sync(0xffffffffu, s, o);
    if (lane == 0) cn[warp] = (float)s;
}

// ============================================================================
// fp32 -> split bf16 (hi + lo), no padding (codebook)
// ============================================================================
__global__ void convert_split(const float* __restrict__ src,
                              __nv_bfloat16* __restrict__ hi,
                              __nv_bfloat16* __restrict__ lo, int n8)
{
    int i = blockIdx.x * blockDim.x + threadIdx.x;
    if (i >= n8) return;
    const float4* s = (const float4*)src + (size_t)i * 2;
    float4 v0 = s[0], v1 = s[1];
    float v[8] = {v0.x, v0.y, v0.z, v0.w, v1.x, v1.y, v1.z, v1.w};
    __nv_bfloat16 h[8], l[8];
    #pragma unroll
    for (int e = 0; e < 8; e++) {
        h[e] = __float2bfloat16_rn(v[e]);
        l[e] = __float2bfloat16_rn(v[e] - __bfloat162float(h[e]));
    }
    uint4 oh, ol;
    oh.x = *(uint32_t*)&h[0]; oh.y = *(uint32_t*)&h[2];
    oh.z = *(uint32_t*)&h[4]; oh.w = *(uint32_t*)&h[6];
    ol.x = *(uint32_t*)&l[0]; ol.y = *(uint32_t*)&l[2];
    ol.z = *(uint32_t*)&l[4]; ol.w = *(uint32_t*)&l[6];
    ((uint4*)hi)[i] = oh;
    ((uint4*)lo)[i] = ol;
}

// ============================================================================
// h2 [8192 x 500] -> split bf16 [8192 x 512] (zero-padded cols 500..511)
// One thread per 4 output cols.
// ============================================================================
__global__ void h2_split(const float* __restrict__ h2,
                         __nv_bfloat16* __restrict__ hh,
                         __nv_bfloat16* __restrict__ hl)
{
    int i = blockIdx.x * blockDim.x + threadIdx.x;   // over 8192*128
    if (i >= BROWS * 128) return;
    int b = i >> 7;
    int c0 = (i & 127) * 4;
    __nv_bfloat16 h[4], l[4];
    #pragma unroll
    for (int e = 0; e < 4; e++) {
        int c = c0 + e;
        float v = (c < HDIM) ? h2[(size_t)b * HDIM + c] : 0.f;
        h[e] = __float2bfloat16_rn(v);
        l[e] = __float2bfloat16_rn(v - __bfloat162float(h[e]));
    }
    uint2 oh, ol;
    oh.x = *(uint32_t*)&h[0]; oh.y = *(uint32_t*)&h[2];
    ol.x = *(uint32_t*)&l[0]; ol.y = *(uint32_t*)&l[2];
    *(uint2*)(hh + (size_t)b * CDIM + c0) = oh;
    *(uint2*)(hl + (size_t)b * CDIM + c0) = ol;
}

// ============================================================================
// W3 [500 x 8192] -> transposed split bf16 [8192 x 512] (k padded 500->512)
// 32x32 smem tile transpose, 256 threads (32x8).
// ============================================================================
__global__ void w3t_split(const float* __restrict__ w3,
                          __nv_bfloat16* __restrict__ th,
                          __nv_bfloat16* __restrict__ tl)
{
    __shared__ float tile[32][33];
    int n0 = blockIdx.x * 32;
    int k0 = blockIdx.y * 32;
    int tx = threadIdx.x & 31;
    int ty = threadIdx.x >> 5;     // 0..7
    #pragma unroll
    for (int r = 0; r < 32; r += 8) {
        int k = k0 + ty + r;
        tile[ty + r][tx] = (k < HDIM) ? w3[(size_t)k * CSDIM + n0 + tx] : 0.f;
    }
    __syncthreads();
    #pragma unroll
    for (int r = 0; r < 32; r += 8) {
        int n = n0 + ty + r;
        int k = k0 + tx;
        float v = tile[tx][ty + r];
        __nv_bfloat16 h = __float2bfloat16_rn(v);
        __nv_bfloat16 l = __float2bfloat16_rn(v - __bfloat162float(h));
        th[(size_t)n * CDIM + k] = h;
        tl[(size_t)n * CDIM + k] = l;
    }
}

// ============================================================================
// SMALL fp32 GEMM: 128x128 block, 8x8/thread, FFMA2. (enc1/enc2/dec2)
// NUMERICS: single fp32 accumulator, ascending-k FFMA (bitwise ref-matching).
// ============================================================================
template<int RELU, int HAS_BIAS>
__global__ __launch_bounds__(256, 2)
void gemm_small(const float* __restrict__ A, const float* __restrict__ Bm,
                const float* __restrict__ bias, float* __restrict__ C,
                int N, int K, int ldc)
{
    __shared__ float As[BK][132];
    __shared__ float Bs[BK][128];

    int tid = threadIdx.x;
    int tr = tid >> 4;
    int tc = tid & 15;
    int row0 = blockIdx.y * 128;
    int col0 = blockIdx.x * 128;

    uint64_t acc2[4][8];
    #pragma unroll
    for (int p = 0; p < 4; p++)
        #pragma unroll
        for (int j = 0; j < 8; j++) acc2[p][j] = 0ull;

    for (int k0 = 0; k0 < K; k0 += BK) {
        #pragma unroll
        for (int e = 0; e < 8; e++) {
            int l = tid + e * 256;
            int m = l >> 4;
            int k = l & 15;
            int gk = k0 + k;
            float v = 0.f;
            if (gk < K) v = A[(size_t)(row0 + m) * K + gk];
            As[k][m] = v;
        }
        #pragma unroll
        for (int e = 0; e < 8; e++) {
            int l = tid + e * 256;
            int k = l >> 7;
            int n = l & 127;
            int gk = k0 + k, gn = col0 + n;
            float v = 0.f;
            if (gk < K && gn < N) v = Bm[(size_t)gk * N + gn];
            Bs[k][n] = v;
        }
        __syncthreads();

        #pragma unroll
        for (int kk = 0; kk < BK; kk++) {
            ulonglong2 va0 = *(const ulonglong2*)(&As[kk][tr * 8]);
            ulonglong2 va1 = *(const ulonglong2*)(&As[kk][tr * 8 + 4]);
            uint64_t ap[4] = {va0.x, va0.y, va1.x, va1.y};
            float4 b0 = *(const float4*)(&Bs[kk][tc * 8]);
            float4 b1 = *(const float4*)(&Bs[kk][tc * 8 + 4]);
            uint64_t bd[8];
            bd[0] = pack_dup(b0.x); bd[1] = pack_dup(b0.y);
            bd[2] = pack_dup(b0.z); bd[3] = pack_dup(b0.w);
            bd[4] = pack_dup(b1.x); bd[5] = pack_dup(b1.y);
            bd[6] = pack_dup(b1.z); bd[7] = pack_dup(b1.w);
            #pragma unroll
            for (int p = 0; p < 4; p++)
                #pragma unroll
                for (int j = 0; j < 8; j++)
                    ffma2(acc2[p][j], ap[p], bd[j]);
        }
        __syncthreads();
    }

    #pragma unroll
    for (int p = 0; p < 4; p++) {
        #pragma unroll
        for (int half = 0; half < 2; half++) {
            int r = row0 + tr * 8 + p * 2 + half;
            #pragma unroll
            for (int j = 0; j < 8; j++) {
                int c = col0 + tc * 8 + j;
                if (c < N) {
                    float2 u = unpack2(acc2[p][j]);
                    float v = half ? u.y : u.x;
                    if (HAS_BIAS) v = __fadd_rn(v, bias[c]);
                    if (RELU) v = fmaxf(v, 0.f);
                    C[(size_t)r * ldc + c] = v;
                }
            }
        }
    }
}

// ============================================================================
// Decoder table: T[s][c][n] = sum_k cb[c][k] * dec_w1[(s*512+k)*500 + n]
// ============================================================================
__global__ __launch_bounds__(256, 2)
void table_gemm(const float* __restrict__ cb, const float* __restrict__ dw1,
                float* __restrict__ table)
{
    const float* A = cb;
    const float* Bm = dw1 + (size_t)blockIdx.z * CDIM * HDIM;
    float* C = table + (size_t)blockIdx.z * CDIM * 512;

    __shared__ float As[BK][132];
    __shared__ float Bs[BK][128];

    int tid = threadIdx.x;
    int tr = tid >> 4;
    int tc = tid & 15;
    int row0 = blockIdx.y * 128;
    int col0 = blockIdx.x * 128;

    uint64_t acc2[4][8];
    #pragma unroll
    for (int p = 0; p < 4; p++)
        #pragma unroll
        for (int j = 0; j < 8; j++) acc2[p][j] = 0ull;

    for (int k0 = 0; k0 < CDIM; k0 += BK) {
        #pragma unroll
        for (int e = 0; e < 8; e++) {
            int l = tid + e * 256;
            int m = l >> 4;
            int k = l & 15;
            As[k][m] = A[(size_t)(row0 + m) * CDIM + k0 + k];
        }
        #pragma unroll
        for (int e = 0; e < 8; e++) {
            int l = tid + e * 256;
            int k = l >> 7;
            int n = l & 127;
            int gn = col0 + n;
            Bs[k][n] = (gn < HDIM) ? Bm[(size_t)(k0 + k) * HDIM + gn] : 0.f;
        }
        __syncthreads();

        #pragma unroll
        for (int kk = 0; kk < BK; kk++) {
            ulonglong2 va0 = *(const ulonglong2*)(&As[kk][tr * 8]);
            ulonglong2 va1 = *(const ulonglong2*)(&As[kk][tr * 8 + 4]);
            uint64_t ap[4] = {va0.x, va0.y, va1.x, va1.y};
            float4 b0 = *(const float4*)(&Bs[kk][tc * 8]);
            float4 b1 = *(const float4*)(&Bs[kk][tc * 8 + 4]);
            uint64_t bd[8];
            bd[0] = pack_dup(b0.x); bd[1] = pack_dup(b0.y);
            bd[2] = pack_dup(b0.z); bd[3] = pack_dup(b0.w);
            bd[4] = pack_dup(b1.x); bd[5] = pack_dup(b1.y);
            bd[6] = pack_dup(b1.z); bd[7] = pack_dup(b1.w);
            #pragma unroll
            for (int p = 0; p < 4; p++)
                #pragma unroll
                for (int j = 0; j < 8; j++)
                    ffma2(acc2[p][j], ap[p], bd[j]);
        }
        __syncthreads();
    }

    #pragma unroll
    for (int p = 0; p < 4; p++) {
        #pragma unroll
        for (int half = 0; half < 2; half++) {
            int r = row0 + tr * 8 + p * 2 + half;
            #pragma unroll
            for (int j = 0; j < 8; j++) {
                int c = col0 + tc * 8 + j;
                if (c < HDIM) {
                    float2 u = unpack2(acc2[p][j]);
                    C[(size_t)r * 512 + c] = half ? u.y : u.x;
                }
            }
        }
    }
}

// ============================================================================
// dec1 via table gather-sum
// ============================================================================
__global__ __launch_bounds__(256, 8)
void dec1_gather(const int* __restrict__ codes, const float* __restrict__ table,
                 const float* __restrict__ db1, float* __restrict__ h1)
{
    int b = blockIdx.x * 2 + (threadIdx.x >> 7);
    int t = threadIdx.x & 127;

    __shared__ int cds[2][16];
    if ((threadIdx.x & 127) < 16)
        cds[threadIdx.x >> 7][threadIdx.x & 127] = codes[b * 16 + (threadIdx.x & 127)];
    __syncthreads();

    if (t >= 125) return;
    const int* cd = cds[threadIdx.x >> 7];

    float4 acc = *(const float4*)(db1 + t * 4);
    #pragma unroll
    for (int s = 0; s < 16; s++) {
        const float4* row = (const float4*)(table + (((size_t)s * CDIM + cd[s]) << 9));
        float4 v = row[t];
        acc.x += v.x; acc.y += v.y; acc.z += v.z; acc.w += v.w;
    }
    acc.x = fmaxf(acc.x, 0.f); acc.y = fmaxf(acc.y, 0.f);
    acc.z = fmaxf(acc.z, 0.f); acc.w = fmaxf(acc.w, 0.f);
    *(float4*)(h1 + (size_t)b * HDIM + t * 4) = acc;
}

// ============================================================================
// SPLIT-bf16 3-term mma GEMM core (validated in R11): C = A.B^T(+bias),
// 128x128 CTA tile, K=512, writes fp32 out and optionally split bf16 outs.
// A rows [LDA=512 bf16], B rows [512 bf16]. WRITE_SPLIT: also emit hi/lo.
// ============================================================================
#define S_LD 40

template<int WRITE_SPLIT, int HAS_BIAS>
__global__ __launch_bounds__(256)
void mma3_gemm(const __nv_bfloat16* __restrict__ ah,
               const __nv_bfloat16* __restrict__ al,
               const __nv_bfloat16* __restrict__ bh,
               const __nv_bfloat16* __restrict__ bl,
               const float* __restrict__ bias,
               float* __restrict__ out, int ldo,
               __nv_bfloat16* __restrict__ out_hi,
               __nv_bfloat16* __restrict__ out_lo)
{
    __shared__ __nv_bfloat16 Ah[128 * S_LD];
    __shared__ __nv_bfloat16 Al[128 * S_LD];
    __shared__ __nv_bfloat16 Bh[128 * S_LD];
    __shared__ __nv_bfloat16 Bl[128 * S_LD];

    int tid  = threadIdx.x;
    int lane = tid & 31;
    int wid  = tid >> 5;
    int g    = lane >> 2;
    int tg   = lane & 3;
    int wm   = (wid >> 1) * 32;
    int wn   = (wid & 1) * 64;
    int row0 = blockIdx.y * 128;
    int col0 = blockIdx.x * 128;

    int lrow  = tid >> 1;
    int lhalf = (tid & 1) * 16;
    const uint4* gAh = (const uint4*)(ah + (size_t)(row0 + lrow) * CDIM + lhalf);
    const uint4* gAl = (const uint4*)(al + (size_t)(row0 + lrow) * CDIM + lhalf);
    const uint4* gBh = (const uint4*)(bh + (size_t)(col0 + lrow) * CDIM + lhalf);
    const uint4* gBl = (const uint4*)(bl + (size_t)(col0 + lrow) * CDIM + lhalf);

    float acc[2][8][4];
    #pragma unroll
    for (int mc = 0; mc < 2; mc++)
        #pragma unroll
        for (int nc = 0; nc < 8; nc++)
            #pragma unroll
            for (int q = 0; q < 4; q++) acc[mc][nc][q] = 0.f;

    const int NT = CDIM / 32;
    for (int t = 0; t < NT; t++) {
        {
            uint4 va0 = gAh[t * 4], va1 = gAh[t * 4 + 1];
            uint4 wa0 = gAl[t * 4], wa1 = gAl[t * 4 + 1];
            uint4 vb0 = gBh[t * 4], vb1 = gBh[t * 4 + 1];
            uint4 wb0 = gBl[t * 4], wb1 = gBl[t * 4 + 1];
            uint2* p;
            p = (uint2*)(&Ah[lrow * S_LD + lhalf]);
            p[0] = make_uint2(va0.x, va0.y); p[1] = make_uint2(va0.z, va0.w);
            p[2] = make_uint2(va1.x, va1.y); p[3] = make_uint2(va1.z, va1.w);
            p = (uint2*)(&Al[lrow * S_LD + lhalf]);
            p[0] = make_uint2(wa0.x, wa0.y); p[1] = make_uint2(wa0.z, wa0.w);
            p[2] = make_uint2(wa1.x, wa1.y); p[3] = make_uint2(wa1.z, wa1.w);
            p = (uint2*)(&Bh[lrow * S_LD + lhalf]);
            p[0] = make_uint2(vb0.x, vb0.y); p[1] = make_uint2(vb0.z, vb0.w);
            p[2] = make_uint2(vb1.x, vb1.y); p[3] = make_uint2(vb1.z, vb1.w);
            p = (uint2*)(&Bl[lrow * S_LD + lhalf]);
            p[0] = make_uint2(wb0.x, wb0.y); p[1] = make_uint2(wb0.z, wb0.w);
            p[2] = make_uint2(wb1.x, wb1.y); p[3] = make_uint2(wb1.z, wb1.w);
        }
        __syncthreads();

        #pragma unroll
        for (int kk0 = 0; kk0 < 32; kk0 += 16) {
            uint32_t ahf[2][4], alf[2][4];
            #pragma unroll
            for (int mc = 0; mc < 2; mc++) {
                int base = (wm + mc * 16 + g) * S_LD + kk0 + 2 * tg;
                ahf[mc][0] = *(const uint32_t*)(&Ah[base]);
                ahf[mc][1] = *(const uint32_t*)(&Ah[base + 8 * S_LD]);
                ahf[mc][2] = *(const uint32_t*)(&Ah[base + 8]);
                ahf[mc][3] = *(const uint32_t*)(&Ah[base + 8 * S_LD + 8]);
                alf[mc][0] = *(const uint32_t*)(&Al[base]);
                alf[mc][1] = *(const uint32_t*)(&Al[base + 8 * S_LD]);
                alf[mc][2] = *(const uint32_t*)(&Al[base + 8]);
                alf[mc][3] = *(const uint32_t*)(&Al[base + 8 * S_LD + 8]);
            }
            #pragma unroll
            for (int nc = 0; nc < 8; nc++) {
                int bbase = (wn + nc * 8 + g) * S_LD + kk0 + 2 * tg;
                uint32_t bh0 = *(const uint32_t*)(&Bh[bbase]);
                uint32_t bh1 = *(const uint32_t*)(&Bh[bbase + 8]);
                uint32_t bl0 = *(const uint32_t*)(&Bl[bbase]);
                uint32_t bl1 = *(const uint32_t*)(&Bl[bbase + 8]);
                #pragma unroll
                for (int mc = 0; mc < 2; mc++) {
                    mma_bf16(acc[mc][nc], ahf[mc], bh0, bh1);
                    mma_bf16(acc[mc][nc], ahf[mc], bl0, bl1);
                    mma_bf16(acc[mc][nc], alf[mc], bh0, bh1);
                }
            }
        }
        __syncthreads();
    }

    #pragma unroll
    for (int mc = 0; mc < 2; mc++) {
        #pragma unroll
        for (int nc = 0; nc < 8; nc++) {
            int r = row0 + wm + mc * 16 + g;
            int c = col0 + wn + nc * 8 + 2 * tg;
            #pragma unroll
            for (int h = 0; h < 2; h++) {      // h=0: row r, h=1: row r+8
                int rr = r + h * 8;
                float v0 = acc[mc][nc][h * 2 + 0];
                float v1 = acc[mc][nc][h * 2 + 1];
                if (HAS_BIAS) {
                    v0 = __fadd_rn(v0, bias[c]);
                    v1 = __fadd_rn(v1, bias[c + 1]);
                }
                *(float2*)(out + (size_t)rr * ldo + c) = make_float2(v0, v1);
                if (WRITE_SPLIT) {
                    __nv_bfloat16 h0 = __float2bfloat16_rn(v0);
                    __nv_bfloat16 h1 = __float2bfloat16_rn(v1);
                    __nv_bfloat16 l0 = __float2bfloat16_rn(v0 - __bfloat162float(h0));
                    __nv_bfloat16 l1 = __float2bfloat16_rn(v1 - __bfloat162float(h1));
                    __nv_bfloat16 ph[2] = {h0, h1};
                    __nv_bfloat16 pl[2] = {l0, l1};
                    *(uint32_t*)(out_hi + (size_t)rr * ldo + c) = *(uint32_t*)ph;
                    *(uint32_t*)(out_lo + (size_t)rr * ldo + c) = *(uint32_t*)pl;
                }
            }
        }
    }
}

// ============================================================================
// zero the ambiguous-row counter (graph-replayable reset)
// ============================================================================
__global__ void zero_amb() { g_amb_count = 0; }

// ============================================================================
// VQ select: one warp per row. Single candidate within band -> code decided.
// Else append row to ambiguous list for exact rescue.
// ============================================================================
__global__ __launch_bounds__(256, 4)
void vq_select(const float* __restrict__ S, const float* __restrict__ cnorm,
               int* __restrict__ codes)
{
    int warp = (blockIdx.x * blockDim.x + threadIdx.x) >> 5;
    int lane = threadIdx.x & 31;
    const float* Srow = S + (size_t)warp * CDIM;

    float dv[16];
    float dmin = 3.4e38f;
    #pragma unroll
    for (int i = 0; i < 16; i++) {
        int j = lane + i * 32;
        float d = cnorm[j] - 2.0f * Srow[j];
        dv[i] = d;
        dmin = fminf(dmin, d);
    }
    #pragma unroll
    for (int o = 16; o > 0; o >>= 1)
        dmin = fminf(dmin, __shfl_xor_sync(0xffffffffu, dmin, o));
    float thresh = dmin + VQ_BAND;

    int cnt = 0;
    int myidx = 0x7fffffff;
    #pragma unroll
    for (int i = 0; i < 16; i++) {
        if (dv[i] <= thresh) {
            cnt++;
            int j = lane + i * 32;
            if (j < myidx) myidx = j;
        }
    }
    int total = cnt;
    int jmin = myidx;
    #pragma unroll
    for (int o = 16; o > 0; o >>= 1) {
        total += __shfl_xor_sync(0xffffffffu, total, o);
        jmin = min(jmin, __shfl_xor_sync(0xffffffffu, jmin, o));
    }

    if (total == 1) {
        if (lane == 0) codes[warp] = jmin;
    } else {
        if (lane == 0) {
            int slot = atomicAdd(&g_amb_count, 1);
            g_amb_rows[slot] = warp;
        }
    }
}

// ============================================================================
// Rescue: one 256-thread block per ambiguous row (grid-stride over the list).
// Recomputes the obs row EXACTLY (ascending-k fmaf + __fadd_rn bias, bitwise
// the reference gemm chain), A in double, then exact d2 for band candidates
// with the validated op order. Output codes bitwise match the full-exact path.
// ============================================================================
__global__ __launch_bounds__(256)
void vq_rescue(const float* __restrict__ h2, const float* __restrict__ w3,
               const float* __restrict__ b3, const float* __restrict__ S,
               const float* __restrict__ cb, const float* __restrict__ cnorm,
               int* __restrict__ codes)
{
    __shared__ float orow[512];
    __shared__ double dsum[256];
    __shared__ float fmn[256];
    __shared__ float bvs[256];
    __shared__ int   bis[256];

    int t = threadIdx.x;
    int cnt = g_amb_count;
    for (int idx = blockIdx.x; idx < cnt; idx += gridDim.x) {
        int row = g_amb_rows[idx];
        int b = row >> 4, s = row & 15;
        const float* h2r = h2 + (size_t)b * HDIM;
        const float* w3b = w3 + (size_t)s * CDIM;

        // exact obs row (cols t, t+256), ascending-k single-accumulator fmaf
        float a0 = 0.f, a1 = 0.f;
        for (int k = 0; k < HDIM; k++) {
            float hv = h2r[k];
            const float* wr = w3b + (size_t)k * CSDIM;
            a0 = fmaf(hv, wr[t], a0);
            a1 = fmaf(hv, wr[t + 256], a1);
        }
        float v0 = __fadd_rn(a0, b3[s * CDIM + t]);
        float v1 = __fadd_rn(a1, b3[s * CDIM + t + 256]);
        orow[t] = v0;
        orow[t + 256] = v1;
        dsum[t] = (double)v0 * v0 + (double)v1 * v1;
        __syncthreads();
        for (int o = 128; o > 0; o >>= 1) {
            if (t < o) dsum[t] += dsum[t + o];
            __syncthreads();
        }
        float A = (float)dsum[0];

        // approx band (identical fp32 ops to vq_select)
        const float* Srow = S + (size_t)row * CDIM;
        float d0 = cnorm[t] - 2.0f * Srow[t];
        float d1 = cnorm[t + 256] - 2.0f * Srow[t + 256];
        fmn[t] = fminf(d0, d1);
        __syncthreads();
        for (int o = 128; o > 0; o >>= 1) {
            if (t < o) fmn[t] = fminf(fmn[t], fmn[t + o]);
            __syncthreads();
        }
        float thresh = fmn[0] + VQ_BAND;

        float bv = 3.4e38f; int bi = CDIM;
        #pragma unroll
        for (int e = 0; e < 2; e++) {
            int j = t + e * 256;
            float dj = e ? d1 : d0;
            if (dj <= thresh) {
                const float* crow = cb + (size_t)j * CDIM;
                float acc = 0.f;
                #pragma unroll 8
                for (int k = 0; k < CDIM; k++)
                    acc = fmaf(orow[k], crow[k], acc);
                float twob = __fmul_rn(2.0f, acc);
                float t2   = __fadd_rn(A, -twob);
                float d    = __fadd_rn(t2, cnorm[j]);
                if (d < bv || (d == bv && j < bi)) { bv = d; bi = j; }
            }
        }
        bvs[t] = bv; bis[t] = bi;
        __syncthreads();
        for (int o = 128; o > 0; o >>= 1) {
            if (t < o) {
                float ov = bvs[t + o]; int oi = bis[t + o];
                if (ov < bvs[t] || (ov == bvs[t] && oi < bis[t])) {
                    bvs[t] = ov; bis[t] = oi;
                }
            }
            __syncthreads();
        }
        if (t == 0) codes[row] = bis[0];
        __syncthreads();
    }
}

// ============================================================================
// latent[row] = codebook[codes[row]]
// ============================================================================
__global__ void gather_latent_kernel(const int* __restrict__ codes,
                                     const float* __restrict__ cb,
                                     float* __restrict__ latent)
{
    int row  = blockIdx.x * 2 + (threadIdx.x >> 7);
    int lane = threadIdx.x & 127;
    int c = codes[row];
    const float4* src = (const float4*)(cb + (size_t)c * CDIM);
    float4* dst = (float4*)(latent + (size_t)row * CDIM);
    dst[lane] = src[lane];
}

// ============================================================================
// launch
// ============================================================================
extern "C" void kernel_launch(void* const* d_in, const int* in_sizes, int n_in,
                              void* d_out, int out_size)
{
    const float* x    = (const float*)d_in[0];
    const float* ew1  = (const float*)d_in[1];
    const float* eb1  = (const float*)d_in[2];
    const float* ew2  = (const float*)d_in[3];
    const float* eb2  = (const float*)d_in[4];
    const float* ew3  = (const float*)d_in[5];
    const float* eb3  = (const float*)d_in[6];
    const float* cb   = (const float*)d_in[7];
    const float* dw1  = (const float*)d_in[8];
    const float* db1  = (const float*)d_in[9];
    const float* dw2  = (const float*)d_in[10];
    const float* db2  = (const float*)d_in[11];

    float* out        = (float*)d_out;
    float* out_recon  = out;                                     // [8192, 784]
    float* out_obs    = out + (size_t)BROWS * DDIM;              // [131072, 512]
    float* out_latent = out_obs + (size_t)BROWS * CSDIM;         // [131072, 512]

    float *h1, *h2, *cn, *tbl, *Sbuf; int *codes;
    __nv_bfloat16 *ohi, *olo, *chi, *clo, *hh, *hl, *w3h, *w3l;
    cudaGetSymbolAddress((void**)&h1, g_h1);
    cudaGetSymbolAddress((void**)&h2, g_h2);
    cudaGetSymbolAddress((void**)&cn, g_cnorm);
    cudaGetSymbolAddress((void**)&tbl, g_table);
    cudaGetSymbolAddress((void**)&Sbuf, g_S);
    cudaGetSymbolAddress((void**)&ohi, g_obs_hi);
    cudaGetSymbolAddress((void**)&olo, g_obs_lo);
    cudaGetSymbolAddress((void**)&chi, g_cb_hi);
    cudaGetSymbolAddress((void**)&clo, g_cb_lo);
    cudaGetSymbolAddress((void**)&hh, g_h2h);
    cudaGetSymbolAddress((void**)&hl, g_h2l);
    cudaGetSymbolAddress((void**)&w3h, g_w3th);
    cudaGetSymbolAddress((void**)&w3l, g_w3tl);
    cudaGetSymbolAddress((void**)&codes, g_codes);

    // codebook- and weight-derived preprocessing (independent of encoder chain)
    zero_amb<<<1, 1>>>();
    cnorm_kernel<<<CDIM / 8, 256>>>(cb, cn);
    convert_split<<<(CDIM * CDIM / 8) / 256, 256>>>(cb, chi, clo, CDIM * CDIM / 8);
    w3t_split<<<dim3(CSDIM / 32, CDIM / 32), 256>>>(ew3, w3h, w3l);
    table_gemm<<<dim3(4, 4, SDIM), 256>>>(cb, dw1, tbl);

    // encoder (exact: enc1, enc2 feed both approx path and rescue)
    gemm_small<1,1><<<dim3(4, 64), 256>>>(x,  ew1, eb1, h1, HDIM, DDIM, HDIM);
    gemm_small<1,1><<<dim3(4, 64), 256>>>(h1, ew2, eb2, h2, HDIM, HDIM, HDIM);

    // enc3 approx on tensor cores: obs = h2 @ W3 + b3 (split-bf16 3-term),
    // epilogue emits obs fp32 + obs_hi/obs_lo directly
    h2_split<<<(BROWS * 128 + 255) / 256, 256>>>(h2, hh, hl);
    mma3_gemm<1,1><<<dim3(CSDIM / 128, BROWS / 128), 256>>>(
        hh, hl, w3h, w3l, eb3, out_obs, CSDIM, ohi, olo);

    // S = obs . cb^T (split-bf16 3-term), then band select + exact rescue
    mma3_gemm<0,0><<<dim3(CDIM / 128, NROWS2 / 128), 256>>>(
        ohi, olo, chi, clo, nullptr, Sbuf, CDIM, nullptr, nullptr);
    vq_select<<<NROWS2 / 8, 256>>>(Sbuf, cn, codes);
    vq_rescue<<<2048, 256>>>(h2, ew3, eb3, Sbuf, cb, cn, codes);
    gather_latent_kernel<<<NROWS2 / 2, 256>>>(codes, cb, out_latent);

    // decoder
    dec1_gather<<<BROWS / 2, 256>>>(codes, tbl, db1, h1);
    gemm_small<0,1><<<dim3(7, 64), 256>>>(h1, dw2, db2, out_recon, DDIM, HDIM, DDIM);
}